// round 11
// baseline (speedup 1.0000x reference)
#include <cuda_runtime.h>
#include <cstdint>

// LDPC min-sum decoder, fully fused, single kernel, ILP=1, f32x2-packed.
// Structure: edge_to_vn = e % N, edge_to_cn = e / 6, N % 6 == 0
// => VN group [6g, 6g+6) touches ONLY CNs {g, g+4096, g+8192}; each (batch,
// group) component is independent; all 10 iterations live in registers.
//
// vs R10: d2 registers dropped (dec recomputed after the loop),
// __launch_bounds__(256, 5) caps regs ~51 -> 5 blocks/SM (62.5% occ),
// pacc update as single FFMA (pacc += pacc*e).

#define B_     128
#define N_     24576
#define ITERS_ 10
#define GRPS   4096
#define TPB    256
#define NBLK   2048            // 2048 x 256 == B_*GRPS exactly
#define CLIP_  20.0f
#define SGNM   0x80000000u

typedef unsigned long long u64;

#define ADD2(out, a, b) \
    asm("add.rn.f32x2 %0, %1, %2;" : "=l"(out) : "l"(a), "l"(b))
#define FMA2(out, a, b, c) \
    asm("fma.rn.f32x2 %0, %1, %2, %3;" : "=l"(out) : "l"(a), "l"(b), "l"(c))
#define PACK2(out, lo, hi) \
    asm("mov.b64 %0, {%1, %2};" : "=l"(out) : "r"(lo), "r"(hi))
#define UNPACK2(lo, hi, in) \
    asm("mov.b64 {%0, %1}, %2;" : "=r"(lo), "=r"(hi) : "l"(in))

__device__ float        g_partial[NBLK];
__device__ unsigned int g_retire = 0;

__global__ __launch_bounds__(TPB, 5) void ldpc_decode_kernel(
    const float* __restrict__ llr_in,
    const float* __restrict__ cn_weight,
    const float* __restrict__ ch_weight,
    const float* __restrict__ cn_bias,
    float* __restrict__ loss_out,   // may be null
    float* __restrict__ dec_out)    // only 4-byte aligned (out+1)
{
    __shared__ float    sh_chw[ITERS_];
    __shared__ float    sh_acnw[ITERS_];
    __shared__ float    sh_cnb[ITERS_];
    __shared__ float    sh_c2[ITERS_];
    __shared__ float    sh_ic2[ITERS_];
    __shared__ unsigned sh_sgnw[ITERS_];

    if (threadIdx.x < ITERS_) {
        float cw   = cn_weight[threadIdx.x];
        float acnw = fabsf(cw);
        float cnb  = cn_bias[threadIdx.x];
        float c2   = fminf(fmaf(CLIP_, acnw, -cnb), CLIP_);
        sh_chw[threadIdx.x]  = ch_weight[threadIdx.x];
        sh_acnw[threadIdx.x] = acnw;
        sh_cnb[threadIdx.x]  = cnb;
        sh_c2[threadIdx.x]   = c2;
        sh_ic2[threadIdx.x]  = 1.0f / c2;
        sh_sgnw[threadIdx.x] = __float_as_uint(cw);
    }
    __syncthreads();

    const int tid = blockIdx.x * TPB + threadIdx.x;   // < B_*GRPS always
    const int b = tid >> 12;
    const int g = tid & (GRPS - 1);
    const size_t off = (size_t)b * N_ + 6 * g;

    // llr as 3 packed pairs (8B aligned: byte offset 4*(b*N + 6g) % 8 == 0)
    u64 llr2[3];
    {
        const u64* p = reinterpret_cast<const u64*>(llr_in + off);
        llr2[0] = p[0]; llr2[1] = p[1]; llr2[2] = p[2];
    }

    u64 c2v2[3][3];     // [cn][pair]
    u64 s2[3];
    #pragma unroll
    for (int p = 0; p < 3; ++p) s2[p] = 0ull;
    #pragma unroll
    for (int k = 0; k < 3; ++k)
        #pragma unroll
        for (int p = 0; p < 3; ++p) c2v2[k][p] = 0ull;

    const u64 NEG1x2 = 0xBF800000BF800000ull;   // (-1.0f, -1.0f)
    float racc = 0.0f;    // sum of (|d| - d)  == 2 * relu(-d)
    float pacc = 1.0f;    // product of (1 + exp(-|d|)), 60 terms <= 2^60

    #pragma unroll 1
    for (int it = 0; it < ITERS_; ++it) {
        const float    chw  = sh_chw[it];
        const float    acnw = sh_acnw[it];
        const float    cnb  = sh_cnb[it];
        const float    c2   = sh_c2[it];
        const float    ic2  = sh_ic2[it];
        const unsigned sgnw = sh_sgnw[it];

        u64 chw2;
        PACK2(chw2, __float_as_uint(chw), __float_as_uint(chw));

        u64 t2[3];
        #pragma unroll
        for (int p = 0; p < 3; ++p)
            FMA2(t2[p], llr2[p], chw2, s2[p]);     // t = llr*chw + s

        #pragma unroll
        for (int k = 0; k < 3; ++k) {
            // r = t - c2v   (packed: r = c2v * (-1) + t)
            u64 r2[3];
            #pragma unroll
            for (int p = 0; p < 3; ++p)
                FMA2(r2[p], c2v2[k][p], NEG1x2, t2[p]);

            unsigned sb[6];
            float u[6];
            #pragma unroll
            for (int p = 0; p < 3; ++p) {
                unsigned lo, hi;
                UNPACK2(lo, hi, r2[p]);
                sb[2*p]   = lo;
                sb[2*p+1] = hi;
                u[2*p]    = fmaf(fabsf(__uint_as_float(lo)), acnw, -cnb);
                u[2*p+1]  = fmaf(fabsf(__uint_as_float(hi)), acnw, -cnb);
            }
            // prefix/suffix mins: ext_j = min over i != j of u_i
            float p1 = fminf(u[0], u[1]);
            float p2 = fminf(p1, u[2]);
            float p3 = fminf(p2, u[3]);
            float p4 = fminf(p3, u[4]);
            float q4 = fminf(u[5], u[4]);
            float q3 = fminf(q4, u[3]);
            float q2 = fminf(q3, u[2]);
            float q1 = fminf(q2, u[1]);
            float ext[6];
            ext[0] = q1;
            ext[1] = fminf(u[0], q2);
            ext[2] = fminf(p1, q3);
            ext[3] = fminf(p2, q4);
            ext[4] = fminf(p3, u[5]);
            ext[5] = p4;
            // sign parity incl. cn_weight sign
            unsigned L3 = (sb[0] ^ sb[1]) ^ (sb[2] ^ sb[3]) ^
                          ((sb[4] ^ sb[5]) ^ sgnw);
            #pragma unroll
            for (int p = 0; p < 3; ++p) {
                float mgl = c2 * __saturatef(ext[2*p]   * ic2);
                float mgh = c2 * __saturatef(ext[2*p+1] * ic2);
                unsigned ol = __float_as_uint(mgl) ^
                              ((L3 ^ sb[2*p])   & SGNM);
                unsigned oh = __float_as_uint(mgh) ^
                              ((L3 ^ sb[2*p+1]) & SGNM);
                PACK2(c2v2[k][p], ol, oh);
            }
        }

        // marginals (packed) + loss accumulation
        #pragma unroll
        for (int p = 0; p < 3; ++p) {
            u64 sn;
            ADD2(sn, c2v2[0][p], c2v2[1][p]);
            ADD2(sn, sn, c2v2[2][p]);
            s2[p] = sn;
            u64 d;
            ADD2(d, llr2[p], sn);
            unsigned lo, hi;
            UNPACK2(lo, hi, d);
            float dl = __uint_as_float(lo);
            float dh = __uint_as_float(hi);
            racc += (fabsf(dl) - dl);
            racc += (fabsf(dh) - dh);
            float el = __expf(-fabsf(dl));
            float eh = __expf(-fabsf(dh));
            pacc = fmaf(pacc, el, pacc);   // pacc *= (1 + el)
            pacc = fmaf(pacc, eh, pacc);   // pacc *= (1 + eh)
        }
    }

    // thread loss: 0.5*racc + log(pacc)
    float lsum = fmaf(racc, 0.5f, __logf(pacc));

    // dec store (scalar: dec_out = out+1 is only 4B aligned);
    // dec recomputed from llr + s (bit-identical to in-loop final d)
    {
        float* o = dec_out + off;
        #pragma unroll
        for (int p = 0; p < 3; ++p) {
            u64 d;
            ADD2(d, llr2[p], s2[p]);
            unsigned lo, hi;
            UNPACK2(lo, hi, d);
            o[2*p]   = __uint_as_float(lo);
            o[2*p+1] = __uint_as_float(hi);
        }
    }

    // ---- loss: block reduce -> partial -> last block reduces all ----
    #pragma unroll
    for (int o2 = 16; o2 > 0; o2 >>= 1)
        lsum += __shfl_down_sync(0xFFFFFFFFu, lsum, o2);

    __shared__ float wsum[8];
    __shared__ bool  is_last;
    const int lane = threadIdx.x & 31;
    const int wid  = threadIdx.x >> 5;
    if (lane == 0) wsum[wid] = lsum;
    __syncthreads();
    if (threadIdx.x == 0) {
        float bs = 0.0f;
        #pragma unroll
        for (int w = 0; w < 8; ++w) bs += wsum[w];
        g_partial[blockIdx.x] = bs;
        __threadfence();
        unsigned ticket = atomicAdd(&g_retire, 1u);
        is_last = (ticket == (unsigned)(gridDim.x - 1));
    }
    __syncthreads();

    if (is_last) {
        float v = 0.0f;
        for (int i = threadIdx.x; i < NBLK; i += TPB)
            v += g_partial[i];
        #pragma unroll
        for (int o2 = 16; o2 > 0; o2 >>= 1)
            v += __shfl_down_sync(0xFFFFFFFFu, v, o2);
        if (lane == 0) wsum[wid] = v;
        __syncthreads();
        if (threadIdx.x == 0) {
            float tot = 0.0f;
            #pragma unroll
            for (int w = 0; w < 8; ++w) tot += wsum[w];
            if (loss_out)
                loss_out[0] = tot * (1.0f / ((float)B_ * (float)N_));
            g_retire = 0;   // restore for next replay (deterministic)
        }
    }
}

extern "C" void kernel_launch(void* const* d_in, const int* in_sizes, int n_in,
                              void* d_out, int out_size) {
    const float* llr_in    = (const float*)d_in[0];
    const float* cn_weight = (const float*)d_in[1];
    const float* ch_weight = (const float*)d_in[2];
    const float* cn_bias   = (const float*)d_in[3];
    // d_in[4], d_in[5]: edge index arrays — structure known analytically.

    float* out = (float*)d_out;
    float* loss_ptr;
    float* dec_ptr;
    if (out_size == B_ * N_ + 1) {     // (loss, dec) flattened
        loss_ptr = out;
        dec_ptr  = out + 1;
    } else {
        loss_ptr = nullptr;
        dec_ptr  = out;
    }

    ldpc_decode_kernel<<<NBLK, TPB>>>(llr_in, cn_weight, ch_weight, cn_bias,
                                      loss_ptr, dec_ptr);
}

// round 12
// speedup vs baseline: 1.0920x; 1.0920x over previous
#include <cuda_runtime.h>
#include <cstdint>

// LDPC min-sum decoder, fully fused, single kernel, ILP=1, f32x2-packed.
// Structure: edge_to_vn = e % N, edge_to_cn = e / 6, N % 6 == 0
// => VN group [6g, 6g+6) touches ONLY CNs {g, g+4096, g+8192}; each (batch,
// group) component is independent; all 10 iterations live in registers.
//
// R12 = R10 config (no occupancy cap: 4 blocks/SM @ ~64 regs, NO spills)
// + d2 registers dropped (dec recomputed after the loop)
// + pacc update as single FFMA (pacc += pacc*e).

#define B_     128
#define N_     24576
#define ITERS_ 10
#define GRPS   4096
#define TPB    256
#define NBLK   2048            // 2048 x 256 == B_*GRPS exactly
#define CLIP_  20.0f
#define SGNM   0x80000000u

typedef unsigned long long u64;

#define ADD2(out, a, b) \
    asm("add.rn.f32x2 %0, %1, %2;" : "=l"(out) : "l"(a), "l"(b))
#define FMA2(out, a, b, c) \
    asm("fma.rn.f32x2 %0, %1, %2, %3;" : "=l"(out) : "l"(a), "l"(b), "l"(c))
#define PACK2(out, lo, hi) \
    asm("mov.b64 %0, {%1, %2};" : "=l"(out) : "r"(lo), "r"(hi))
#define UNPACK2(lo, hi, in) \
    asm("mov.b64 {%0, %1}, %2;" : "=r"(lo), "=r"(hi) : "l"(in))

__device__ float        g_partial[NBLK];
__device__ unsigned int g_retire = 0;

__global__ __launch_bounds__(TPB) void ldpc_decode_kernel(
    const float* __restrict__ llr_in,
    const float* __restrict__ cn_weight,
    const float* __restrict__ ch_weight,
    const float* __restrict__ cn_bias,
    float* __restrict__ loss_out,   // may be null
    float* __restrict__ dec_out)    // only 4-byte aligned (out+1)
{
    __shared__ float    sh_chw[ITERS_];
    __shared__ float    sh_acnw[ITERS_];
    __shared__ float    sh_cnb[ITERS_];
    __shared__ float    sh_c2[ITERS_];
    __shared__ float    sh_ic2[ITERS_];
    __shared__ unsigned sh_sgnw[ITERS_];

    if (threadIdx.x < ITERS_) {
        float cw   = cn_weight[threadIdx.x];
        float acnw = fabsf(cw);
        float cnb  = cn_bias[threadIdx.x];
        float c2   = fminf(fmaf(CLIP_, acnw, -cnb), CLIP_);
        sh_chw[threadIdx.x]  = ch_weight[threadIdx.x];
        sh_acnw[threadIdx.x] = acnw;
        sh_cnb[threadIdx.x]  = cnb;
        sh_c2[threadIdx.x]   = c2;
        sh_ic2[threadIdx.x]  = 1.0f / c2;
        sh_sgnw[threadIdx.x] = __float_as_uint(cw);
    }
    __syncthreads();

    const int tid = blockIdx.x * TPB + threadIdx.x;   // < B_*GRPS always
    const int b = tid >> 12;
    const int g = tid & (GRPS - 1);
    const size_t off = (size_t)b * N_ + 6 * g;

    // llr as 3 packed pairs (8B aligned: byte offset 4*(b*N + 6g) % 8 == 0)
    u64 llr2[3];
    {
        const u64* p = reinterpret_cast<const u64*>(llr_in + off);
        llr2[0] = p[0]; llr2[1] = p[1]; llr2[2] = p[2];
    }

    u64 c2v2[3][3];     // [cn][pair]
    u64 s2[3];
    #pragma unroll
    for (int p = 0; p < 3; ++p) s2[p] = 0ull;
    #pragma unroll
    for (int k = 0; k < 3; ++k)
        #pragma unroll
        for (int p = 0; p < 3; ++p) c2v2[k][p] = 0ull;

    const u64 NEG1x2 = 0xBF800000BF800000ull;   // (-1.0f, -1.0f)
    float racc = 0.0f;    // sum of (|d| - d)  == 2 * relu(-d)
    float pacc = 1.0f;    // product of (1 + exp(-|d|)), 60 terms <= 2^60

    #pragma unroll 1
    for (int it = 0; it < ITERS_; ++it) {
        const float    chw  = sh_chw[it];
        const float    acnw = sh_acnw[it];
        const float    cnb  = sh_cnb[it];
        const float    c2   = sh_c2[it];
        const float    ic2  = sh_ic2[it];
        const unsigned sgnw = sh_sgnw[it];

        u64 chw2;
        PACK2(chw2, __float_as_uint(chw), __float_as_uint(chw));

        u64 t2[3];
        #pragma unroll
        for (int p = 0; p < 3; ++p)
            FMA2(t2[p], llr2[p], chw2, s2[p]);     // t = llr*chw + s

        #pragma unroll
        for (int k = 0; k < 3; ++k) {
            // r = t - c2v   (packed: r = c2v * (-1) + t)
            u64 r2[3];
            #pragma unroll
            for (int p = 0; p < 3; ++p)
                FMA2(r2[p], c2v2[k][p], NEG1x2, t2[p]);

            unsigned sb[6];
            float u[6];
            #pragma unroll
            for (int p = 0; p < 3; ++p) {
                unsigned lo, hi;
                UNPACK2(lo, hi, r2[p]);
                sb[2*p]   = lo;
                sb[2*p+1] = hi;
                u[2*p]    = fmaf(fabsf(__uint_as_float(lo)), acnw, -cnb);
                u[2*p+1]  = fmaf(fabsf(__uint_as_float(hi)), acnw, -cnb);
            }
            // prefix/suffix mins: ext_j = min over i != j of u_i
            float p1 = fminf(u[0], u[1]);
            float p2 = fminf(p1, u[2]);
            float p3 = fminf(p2, u[3]);
            float p4 = fminf(p3, u[4]);
            float q4 = fminf(u[5], u[4]);
            float q3 = fminf(q4, u[3]);
            float q2 = fminf(q3, u[2]);
            float q1 = fminf(q2, u[1]);
            float ext[6];
            ext[0] = q1;
            ext[1] = fminf(u[0], q2);
            ext[2] = fminf(p1, q3);
            ext[3] = fminf(p2, q4);
            ext[4] = fminf(p3, u[5]);
            ext[5] = p4;
            // sign parity incl. cn_weight sign
            unsigned L3 = (sb[0] ^ sb[1]) ^ (sb[2] ^ sb[3]) ^
                          ((sb[4] ^ sb[5]) ^ sgnw);
            #pragma unroll
            for (int p = 0; p < 3; ++p) {
                float mgl = c2 * __saturatef(ext[2*p]   * ic2);
                float mgh = c2 * __saturatef(ext[2*p+1] * ic2);
                unsigned ol = __float_as_uint(mgl) ^
                              ((L3 ^ sb[2*p])   & SGNM);
                unsigned oh = __float_as_uint(mgh) ^
                              ((L3 ^ sb[2*p+1]) & SGNM);
                PACK2(c2v2[k][p], ol, oh);
            }
        }

        // marginals (packed) + loss accumulation
        #pragma unroll
        for (int p = 0; p < 3; ++p) {
            u64 sn;
            ADD2(sn, c2v2[0][p], c2v2[1][p]);
            ADD2(sn, sn, c2v2[2][p]);
            s2[p] = sn;
            u64 d;
            ADD2(d, llr2[p], sn);
            unsigned lo, hi;
            UNPACK2(lo, hi, d);
            float dl = __uint_as_float(lo);
            float dh = __uint_as_float(hi);
            racc += (fabsf(dl) - dl);
            racc += (fabsf(dh) - dh);
            float el = __expf(-fabsf(dl));
            float eh = __expf(-fabsf(dh));
            pacc = fmaf(pacc, el, pacc);   // pacc *= (1 + el)
            pacc = fmaf(pacc, eh, pacc);   // pacc *= (1 + eh)
        }
    }

    // thread loss: 0.5*racc + log(pacc)
    float lsum = fmaf(racc, 0.5f, __logf(pacc));

    // dec store (scalar: dec_out = out+1 is only 4B aligned);
    // dec recomputed from llr + s (bit-identical to in-loop final d)
    {
        float* o = dec_out + off;
        #pragma unroll
        for (int p = 0; p < 3; ++p) {
            u64 d;
            ADD2(d, llr2[p], s2[p]);
            unsigned lo, hi;
            UNPACK2(lo, hi, d);
            o[2*p]   = __uint_as_float(lo);
            o[2*p+1] = __uint_as_float(hi);
        }
    }

    // ---- loss: block reduce -> partial -> last block reduces all ----
    #pragma unroll
    for (int o2 = 16; o2 > 0; o2 >>= 1)
        lsum += __shfl_down_sync(0xFFFFFFFFu, lsum, o2);

    __shared__ float wsum[8];
    __shared__ bool  is_last;
    const int lane = threadIdx.x & 31;
    const int wid  = threadIdx.x >> 5;
    if (lane == 0) wsum[wid] = lsum;
    __syncthreads();
    if (threadIdx.x == 0) {
        float bs = 0.0f;
        #pragma unroll
        for (int w = 0; w < 8; ++w) bs += wsum[w];
        g_partial[blockIdx.x] = bs;
        __threadfence();
        unsigned ticket = atomicAdd(&g_retire, 1u);
        is_last = (ticket == (unsigned)(gridDim.x - 1));
    }
    __syncthreads();

    if (is_last) {
        float v = 0.0f;
        for (int i = threadIdx.x; i < NBLK; i += TPB)
            v += g_partial[i];
        #pragma unroll
        for (int o2 = 16; o2 > 0; o2 >>= 1)
            v += __shfl_down_sync(0xFFFFFFFFu, v, o2);
        if (lane == 0) wsum[wid] = v;
        __syncthreads();
        if (threadIdx.x == 0) {
            float tot = 0.0f;
            #pragma unroll
            for (int w = 0; w < 8; ++w) tot += wsum[w];
            if (loss_out)
                loss_out[0] = tot * (1.0f / ((float)B_ * (float)N_));
            g_retire = 0;   // restore for next replay (deterministic)
        }
    }
}

extern "C" void kernel_launch(void* const* d_in, const int* in_sizes, int n_in,
                              void* d_out, int out_size) {
    const float* llr_in    = (const float*)d_in[0];
    const float* cn_weight = (const float*)d_in[1];
    const float* ch_weight = (const float*)d_in[2];
    const float* cn_bias   = (const float*)d_in[3];
    // d_in[4], d_in[5]: edge index arrays — structure known analytically.

    float* out = (float*)d_out;
    float* loss_ptr;
    float* dec_ptr;
    if (out_size == B_ * N_ + 1) {     // (loss, dec) flattened
        loss_ptr = out;
        dec_ptr  = out + 1;
    } else {
        loss_ptr = nullptr;
        dec_ptr  = out;
    }

    ldpc_decode_kernel<<<NBLK, TPB>>>(llr_in, cn_weight, ch_weight, cn_bias,
                                      loss_ptr, dec_ptr);
}

// round 13
// speedup vs baseline: 1.1434x; 1.0471x over previous
#include <cuda_runtime.h>
#include <cstdint>

// LDPC min-sum decoder, fully fused, single kernel, ILP=1, f32x2-packed.
// Structure: edge_to_vn = e % N, edge_to_cn = e / 6, N % 6 == 0
// => VN group [6g, 6g+6) touches ONLY CNs {g, g+4096, g+8192}; each (batch,
// group) component is independent; all 10 iterations live in registers.
//
// vs R12: tournament runs on |r| (FMNMX abs modifiers, free); the monotone
// magnitude map ext*w - b is folded into the clamp as one FFMA.SAT + FMUL
// per edge (wic = |w|/c2, bic = b/c2 precomputed) -> the 18 per-edge FFMAs
// are gone. Loss: sum(|d|-d) split into packed sum(d) + scalar sum(|d|).

#define B_     128
#define N_     24576
#define ITERS_ 10
#define GRPS   4096
#define TPB    256
#define NBLK   2048            // 2048 x 256 == B_*GRPS exactly
#define CLIP_  20.0f
#define SGNM   0x80000000u

typedef unsigned long long u64;

#define ADD2(out, a, b) \
    asm("add.rn.f32x2 %0, %1, %2;" : "=l"(out) : "l"(a), "l"(b))
#define FMA2(out, a, b, c) \
    asm("fma.rn.f32x2 %0, %1, %2, %3;" : "=l"(out) : "l"(a), "l"(b), "l"(c))
#define PACK2(out, lo, hi) \
    asm("mov.b64 %0, {%1, %2};" : "=l"(out) : "r"(lo), "r"(hi))
#define UNPACK2(lo, hi, in) \
    asm("mov.b64 {%0, %1}, %2;" : "=r"(lo), "=r"(hi) : "l"(in))

__device__ float        g_partial[NBLK];
__device__ unsigned int g_retire = 0;

__global__ __launch_bounds__(TPB) void ldpc_decode_kernel(
    const float* __restrict__ llr_in,
    const float* __restrict__ cn_weight,
    const float* __restrict__ ch_weight,
    const float* __restrict__ cn_bias,
    float* __restrict__ loss_out,   // may be null
    float* __restrict__ dec_out)    // only 4-byte aligned (out+1)
{
    __shared__ float    sh_chw[ITERS_];
    __shared__ float    sh_wic[ITERS_];   // |cn_w| / c2
    __shared__ float    sh_bic[ITERS_];   // cn_b / c2
    __shared__ float    sh_c2[ITERS_];    // min(20*|w| - b, 20)
    __shared__ unsigned sh_sgnw[ITERS_];

    if (threadIdx.x < ITERS_) {
        float cw   = cn_weight[threadIdx.x];
        float acnw = fabsf(cw);
        float cnb  = cn_bias[threadIdx.x];
        float c2   = fminf(fmaf(CLIP_, acnw, -cnb), CLIP_);
        float ic2  = 1.0f / c2;
        sh_chw[threadIdx.x]  = ch_weight[threadIdx.x];
        sh_wic[threadIdx.x]  = acnw * ic2;
        sh_bic[threadIdx.x]  = cnb * ic2;
        sh_c2[threadIdx.x]   = c2;
        sh_sgnw[threadIdx.x] = __float_as_uint(cw);
    }
    __syncthreads();

    const int tid = blockIdx.x * TPB + threadIdx.x;   // < B_*GRPS always
    const int b = tid >> 12;
    const int g = tid & (GRPS - 1);
    const size_t off = (size_t)b * N_ + 6 * g;

    // llr as 3 packed pairs (8B aligned: byte offset 4*(b*N + 6g) % 8 == 0)
    u64 llr2[3];
    {
        const u64* p = reinterpret_cast<const u64*>(llr_in + off);
        llr2[0] = p[0]; llr2[1] = p[1]; llr2[2] = p[2];
    }

    u64 c2v2[3][3];     // [cn][pair]
    u64 s2[3];
    #pragma unroll
    for (int p = 0; p < 3; ++p) s2[p] = 0ull;
    #pragma unroll
    for (int k = 0; k < 3; ++k)
        #pragma unroll
        for (int p = 0; p < 3; ++p) c2v2[k][p] = 0ull;

    const u64 NEG1x2 = 0xBF800000BF800000ull;   // (-1.0f, -1.0f)
    u64   dacc2 = 0ull;   // packed sum of d (both lanes)
    float aacc  = 0.0f;   // sum of |d|
    float pacc  = 1.0f;   // product of (1 + exp(-|d|)), 60 terms <= 2^60

    #pragma unroll 1
    for (int it = 0; it < ITERS_; ++it) {
        const float    chw  = sh_chw[it];
        const float    wic  = sh_wic[it];
        const float    bic  = sh_bic[it];
        const float    c2   = sh_c2[it];
        const unsigned sgnw = sh_sgnw[it];

        u64 chw2;
        PACK2(chw2, __float_as_uint(chw), __float_as_uint(chw));

        u64 t2[3];
        #pragma unroll
        for (int p = 0; p < 3; ++p)
            FMA2(t2[p], llr2[p], chw2, s2[p]);     // t = llr*chw + s

        #pragma unroll
        for (int k = 0; k < 3; ++k) {
            // r = t - c2v   (packed: r = c2v * (-1) + t)
            u64 r2[3];
            #pragma unroll
            for (int p = 0; p < 3; ++p)
                FMA2(r2[p], c2v2[k][p], NEG1x2, t2[p]);

            unsigned sb[6];
            float ar[6];
            #pragma unroll
            for (int p = 0; p < 3; ++p) {
                unsigned lo, hi;
                UNPACK2(lo, hi, r2[p]);
                sb[2*p]   = lo;
                sb[2*p+1] = hi;
                ar[2*p]   = fabsf(__uint_as_float(lo));   // |.| folds into FMNMX
                ar[2*p+1] = fabsf(__uint_as_float(hi));
            }
            // prefix/suffix mins on |r|: ext_j = min over i != j of |r_i|
            float p1 = fminf(ar[0], ar[1]);
            float p2 = fminf(p1, ar[2]);
            float p3 = fminf(p2, ar[3]);
            float p4 = fminf(p3, ar[4]);
            float q4 = fminf(ar[5], ar[4]);
            float q3 = fminf(q4, ar[3]);
            float q2 = fminf(q3, ar[2]);
            float q1 = fminf(q2, ar[1]);
            float ext[6];
            ext[0] = q1;
            ext[1] = fminf(ar[0], q2);
            ext[2] = fminf(p1, q3);
            ext[3] = fminf(p2, q4);
            ext[4] = fminf(p3, ar[5]);
            ext[5] = p4;
            // sign parity incl. cn_weight sign
            unsigned L3 = (sb[0] ^ sb[1]) ^ (sb[2] ^ sb[3]) ^
                          ((sb[4] ^ sb[5]) ^ sgnw);
            #pragma unroll
            for (int p = 0; p < 3; ++p) {
                // mg = clamp(ext*|w| - b, 0, c2) = c2 * sat(ext*wic - bic)
                float mgl = c2 * __saturatef(fmaf(ext[2*p],   wic, -bic));
                float mgh = c2 * __saturatef(fmaf(ext[2*p+1], wic, -bic));
                unsigned ol = __float_as_uint(mgl) ^
                              ((L3 ^ sb[2*p])   & SGNM);
                unsigned oh = __float_as_uint(mgh) ^
                              ((L3 ^ sb[2*p+1]) & SGNM);
                PACK2(c2v2[k][p], ol, oh);
            }
        }

        // marginals (packed) + loss accumulation
        #pragma unroll
        for (int p = 0; p < 3; ++p) {
            u64 sn;
            ADD2(sn, c2v2[0][p], c2v2[1][p]);
            ADD2(sn, sn, c2v2[2][p]);
            s2[p] = sn;
            u64 d;
            ADD2(d, llr2[p], sn);
            ADD2(dacc2, dacc2, d);
            unsigned lo, hi;
            UNPACK2(lo, hi, d);
            float dl = __uint_as_float(lo);
            float dh = __uint_as_float(hi);
            aacc += fabsf(dl);
            aacc += fabsf(dh);
            float el = __expf(-fabsf(dl));
            float eh = __expf(-fabsf(dh));
            pacc = fmaf(pacc, el, pacc);   // pacc *= (1 + el)
            pacc = fmaf(pacc, eh, pacc);   // pacc *= (1 + eh)
        }
    }

    // thread loss: 0.5*(sum|d| - sum d) + log(pacc)
    float lsum;
    {
        unsigned lo, hi;
        UNPACK2(lo, hi, dacc2);
        float dsum = __uint_as_float(lo) + __uint_as_float(hi);
        lsum = fmaf(aacc - dsum, 0.5f, __logf(pacc));
    }

    // dec store (scalar: dec_out = out+1 is only 4B aligned);
    // dec recomputed from llr + s (bit-identical to in-loop final d)
    {
        float* o = dec_out + off;
        #pragma unroll
        for (int p = 0; p < 3; ++p) {
            u64 d;
            ADD2(d, llr2[p], s2[p]);
            unsigned lo, hi;
            UNPACK2(lo, hi, d);
            o[2*p]   = __uint_as_float(lo);
            o[2*p+1] = __uint_as_float(hi);
        }
    }

    // ---- loss: block reduce -> partial -> last block reduces all ----
    #pragma unroll
    for (int o2 = 16; o2 > 0; o2 >>= 1)
        lsum += __shfl_down_sync(0xFFFFFFFFu, lsum, o2);

    __shared__ float wsum[8];
    __shared__ bool  is_last;
    const int lane = threadIdx.x & 31;
    const int wid  = threadIdx.x >> 5;
    if (lane == 0) wsum[wid] = lsum;
    __syncthreads();
    if (threadIdx.x == 0) {
        float bs = 0.0f;
        #pragma unroll
        for (int w = 0; w < 8; ++w) bs += wsum[w];
        g_partial[blockIdx.x] = bs;
        __threadfence();
        unsigned ticket = atomicAdd(&g_retire, 1u);
        is_last = (ticket == (unsigned)(gridDim.x - 1));
    }
    __syncthreads();

    if (is_last) {
        float v = 0.0f;
        for (int i = threadIdx.x; i < NBLK; i += TPB)
            v += g_partial[i];
        #pragma unroll
        for (int o2 = 16; o2 > 0; o2 >>= 1)
            v += __shfl_down_sync(0xFFFFFFFFu, v, o2);
        if (lane == 0) wsum[wid] = v;
        __syncthreads();
        if (threadIdx.x == 0) {
            float tot = 0.0f;
            #pragma unroll
            for (int w = 0; w < 8; ++w) tot += wsum[w];
            if (loss_out)
                loss_out[0] = tot * (1.0f / ((float)B_ * (float)N_));
            g_retire = 0;   // restore for next replay (deterministic)
        }
    }
}

extern "C" void kernel_launch(void* const* d_in, const int* in_sizes, int n_in,
                              void* d_out, int out_size) {
    const float* llr_in    = (const float*)d_in[0];
    const float* cn_weight = (const float*)d_in[1];
    const float* ch_weight = (const float*)d_in[2];
    const float* cn_bias   = (const float*)d_in[3];
    // d_in[4], d_in[5]: edge index arrays — structure known analytically.

    float* out = (float*)d_out;
    float* loss_ptr;
    float* dec_ptr;
    if (out_size == B_ * N_ + 1) {     // (loss, dec) flattened
        loss_ptr = out;
        dec_ptr  = out + 1;
    } else {
        loss_ptr = nullptr;
        dec_ptr  = out;
    }

    ldpc_decode_kernel<<<NBLK, TPB>>>(llr_in, cn_weight, ch_weight, cn_bias,
                                      loss_ptr, dec_ptr);
}